// round 8
// baseline (speedup 1.0000x reference)
#include <cuda_runtime.h>
#include <cuda_bf16.h>

#define NN 50000
#define EE 600000
#define HH 128
#define NG 64

// ---------------- static scratch (allocation-free rule) ----------------
__device__ float g_hA[NN * HH];
__device__ float g_hB[NN * HH];
__device__ int   g_deg[3][NN];
__device__ int   g_off[3][NN + 1];
__device__ int   g_cur[3][NN];
__device__ int   g_csr[3][EE];
__device__ float g_pool[NG * HH];
// bf16 weight images, transposed to [n][k] row-major, unpadded 32KB each:
// [conv][mat(Wl=0,Wr=1)][hi=0/lo=1]
__device__ __align__(16) __nv_bfloat16 g_wblob[5][2][2][HH * HH];

// ---------------- CSR build ----------------
__global__ void k_zero_deg() {
    int i = blockIdx.x * blockDim.x + threadIdx.x;
    if (i < 3 * NN) ((int*)g_deg)[i] = 0;
}
__global__ void k_hist(const int* __restrict__ e0, const int* __restrict__ e1,
                       const int* __restrict__ e2) {
    int i = blockIdx.x * blockDim.x + threadIdx.x;
    if (i >= EE) return;
    atomicAdd(&g_deg[0][e0[EE + i]], 1);
    atomicAdd(&g_deg[1][e1[EE + i]], 1);
    atomicAdd(&g_deg[2][e2[EE + i]], 1);
}
__global__ void k_scan() {
    int lst = blockIdx.x;
    __shared__ int wsum[32];
    __shared__ int carry;
    int t = threadIdx.x, wid = t >> 5, lane = t & 31;
    if (t == 0) carry = 0;
    __syncthreads();
    for (int base = 0; base < NN; base += 1024) {
        int i = base + t;
        int v = (i < NN) ? g_deg[lst][i] : 0;
        int x = v;
#pragma unroll
        for (int o = 1; o < 32; o <<= 1) {
            int y = __shfl_up_sync(0xffffffffu, x, o);
            if (lane >= o) x += y;
        }
        __syncthreads();
        if (lane == 31) wsum[wid] = x;
        __syncthreads();
        if (t < 32) {
            int xx = wsum[t];
#pragma unroll
            for (int o = 1; o < 32; o <<= 1) {
                int y = __shfl_up_sync(0xffffffffu, xx, o);
                if (t >= o) xx += y;
            }
            wsum[t] = xx;
        }
        __syncthreads();
        int wb = wid ? wsum[wid - 1] : 0;
        int excl = carry + wb + x - v;
        if (i < NN) { g_off[lst][i] = excl; g_cur[lst][i] = excl; }
        __syncthreads();
        if (t == 0) carry += wsum[31];
        __syncthreads();
    }
    if (t == 0) g_off[lst][NN] = carry;
}
// all 3 lists in one launch
__global__ void k_fill3(const int* __restrict__ e0, const int* __restrict__ e1,
                        const int* __restrict__ e2) {
    int i = blockIdx.x * blockDim.x + threadIdx.x;
    if (i < EE) {
        int d = e0[EE + i];
        g_csr[0][atomicAdd(&g_cur[0][d], 1)] = e0[i];
    } else if (i < 2 * EE) {
        int j = i - EE;
        int d = e1[EE + j];
        g_csr[1][atomicAdd(&g_cur[1][d], 1)] = e1[j];
    } else if (i < 3 * EE) {
        int j = i - 2 * EE;
        int d = e2[EE + j];
        g_csr[2][atomicAdd(&g_cur[2][d], 1)] = e2[j];
    }
}

// ---------------- weight prep: all 10 matrices in one launch ----------------
struct WP { const float* p[10]; };
__global__ void k_wprep_all(WP wp) {
    int idx = blockIdx.x * blockDim.x + threadIdx.x;  // 0..163839
    int m = idx >> 14;            // 0..9 -> conv*2 + mat
    int r = idx & 16383;
    int n = r >> 7, k = r & 127;
    const float* W = wp.p[m];
    float v = W[k * 128 + n];
    __nv_bfloat16 hi = __float2bfloat16(v);
    __nv_bfloat16 lo = __float2bfloat16(v - __bfloat162float(hi));
    int c = m >> 1, mat = m & 1;
    g_wblob[c][mat][0][n * 128 + k] = hi;
    g_wblob[c][mat][1][n * 128 + k] = lo;
}

// ---------------- fused agg + mma.sync bf16 SAGE GEMM ----------------
// out[128 x 128] = mean_agg(hin)@Wl + hin@Wr + bl (+ optional row L2 norm)
// 3-term bf16 split per phase: hi*hi + lo*hi + hi*lo, fp32 accum.
// SMEM: 4 bf16 tiles [128][128], row stride 272B -> LDS/LDSM conflict-free.
#define PADW 68
#define TILE_B (128 * PADW * 4)
#define OFF_AHI 0
#define OFF_ALO TILE_B
#define OFF_WHI (2 * TILE_B)
#define OFF_WLO (3 * TILE_B)
#define SM_TOTAL (4 * TILE_B)
#define CSTRIDE 132

__device__ __forceinline__ unsigned smem_u32(const void* p) {
    unsigned a;
    asm("{ .reg .u64 t; cvta.to.shared.u64 t, %1; cvt.u32.u64 %0, t; }" : "=r"(a) : "l"(p));
    return a;
}
__device__ __forceinline__ void mma16816(float* c, const unsigned* a, const unsigned* b) {
    asm volatile(
        "mma.sync.aligned.m16n8k16.row.col.f32.bf16.bf16.f32 "
        "{%0,%1,%2,%3}, {%4,%5,%6,%7}, {%8,%9}, {%0,%1,%2,%3};"
        : "+f"(c[0]), "+f"(c[1]), "+f"(c[2]), "+f"(c[3])
        : "r"(a[0]), "r"(a[1]), "r"(a[2]), "r"(a[3]), "r"(b[0]), "r"(b[1]));
}
__device__ __forceinline__ void ldsm4(unsigned& r0, unsigned& r1, unsigned& r2,
                                      unsigned& r3, unsigned addr) {
    asm volatile("ldmatrix.sync.aligned.m8n8.x4.shared.b16 {%0,%1,%2,%3}, [%4];"
                 : "=r"(r0), "=r"(r1), "=r"(r2), "=r"(r3) : "r"(addr));
}

__global__ __launch_bounds__(256, 1) void k_sage_mma(
    const float* __restrict__ hin, const float* __restrict__ bl,
    int conv, int lst, float* __restrict__ out, int donorm) {
    extern __shared__ char smem[];
    const unsigned sb = smem_u32(smem);
    const int tid = threadIdx.x;
    const int wid = tid >> 5, lane = tid & 31;
    const int m0 = (wid >> 1) * 32;       // warp m-origin
    const int n0 = (wid & 1) * 64;        // warp n-origin
    const int rowBase = blockIdx.x * 128;

    float acc[2][8][4];
#pragma unroll
    for (int mi = 0; mi < 2; mi++)
#pragma unroll
        for (int ni = 0; ni < 8; ni++)
#pragma unroll
            for (int r = 0; r < 4; r++) acc[mi][ni][r] = 0.f;

    // per-lane ldmatrix base offsets (bytes within a tile)
    const int i4 = lane >> 3, r8 = lane & 7;
    const unsigned aoff = (unsigned)(m0 + (i4 & 1) * 8 + r8) * 272 + (i4 >> 1) * 16;
    const unsigned boff = (unsigned)(n0 + (i4 >> 1) * 8 + r8) * 272 + (i4 & 1) * 16;

#pragma unroll 1
    for (int phase = 0; phase < 2; phase++) {
        // --- A tile fill ---
        if (phase == 0) {
            // fused mean aggregation: warp w handles rows w*16..w*16+15
            const int* off = g_off[lst];
            const int* csr = g_csr[lst];
#pragma unroll 1
            for (int i = 0; i < 16; i++) {
                int r = wid * 16 + i;
                int node = rowBase + r;
                float4 acc4 = make_float4(0.f, 0.f, 0.f, 0.f);
                float inv = 0.f;
                if (node < NN) {
                    int s = off[node], e = off[node + 1];
#pragma unroll 2
                    for (int j = s; j < e; j++) {
                        int src = csr[j];
                        float4 v = __ldg((const float4*)(hin + (size_t)src * HH + lane * 4));
                        acc4.x += v.x; acc4.y += v.y; acc4.z += v.z; acc4.w += v.w;
                    }
                    inv = 1.0f / fmaxf((float)(e - s), 1.0f);
                }
                acc4.x *= inv; acc4.y *= inv; acc4.z *= inv; acc4.w *= inv;
                __nv_bfloat162 h0, h1, l0, l1;
                h0.x = __float2bfloat16(acc4.x); h0.y = __float2bfloat16(acc4.y);
                h1.x = __float2bfloat16(acc4.z); h1.y = __float2bfloat16(acc4.w);
                l0.x = __float2bfloat16(acc4.x - __bfloat162float(h0.x));
                l0.y = __float2bfloat16(acc4.y - __bfloat162float(h0.y));
                l1.x = __float2bfloat16(acc4.z - __bfloat162float(h1.x));
                l1.y = __float2bfloat16(acc4.w - __bfloat162float(h1.y));
                unsigned so = (unsigned)r * 272 + lane * 8;
                *(__nv_bfloat162*)(smem + OFF_AHI + so)     = h0;
                *(__nv_bfloat162*)(smem + OFF_AHI + so + 4) = h1;
                *(__nv_bfloat162*)(smem + OFF_ALO + so)     = l0;
                *(__nv_bfloat162*)(smem + OFF_ALO + so + 4) = l1;
            }
        } else {
            // direct rows of hin
#pragma unroll 4
            for (int i = 0; i < 16; i++) {
                int v = i * 256 + tid;
                int r = v >> 5, c4 = v & 31;
                int grow = rowBase + r;
                float4 f = make_float4(0.f, 0.f, 0.f, 0.f);
                if (grow < NN) f = __ldg((const float4*)(hin + (size_t)grow * HH + c4 * 4));
                __nv_bfloat162 h0, h1, l0, l1;
                h0.x = __float2bfloat16(f.x); h0.y = __float2bfloat16(f.y);
                h1.x = __float2bfloat16(f.z); h1.y = __float2bfloat16(f.w);
                l0.x = __float2bfloat16(f.x - __bfloat162float(h0.x));
                l0.y = __float2bfloat16(f.y - __bfloat162float(h0.y));
                l1.x = __float2bfloat16(f.z - __bfloat162float(h1.x));
                l1.y = __float2bfloat16(f.w - __bfloat162float(h1.y));
                unsigned so = (unsigned)r * 272 + c4 * 8;
                *(__nv_bfloat162*)(smem + OFF_AHI + so)     = h0;
                *(__nv_bfloat162*)(smem + OFF_AHI + so + 4) = h1;
                *(__nv_bfloat162*)(smem + OFF_ALO + so)     = l0;
                *(__nv_bfloat162*)(smem + OFF_ALO + so + 4) = l1;
            }
        }
        // --- W tiles: copy hi/lo blobs into padded SMEM ---
        {
            const uint4* bh = (const uint4*)g_wblob[conv][phase][0];
            const uint4* bo = (const uint4*)g_wblob[conv][phase][1];
            uint4* wh = (uint4*)(smem + OFF_WHI);
            uint4* wl = (uint4*)(smem + OFF_WLO);
#pragma unroll 4
            for (int i = 0; i < 8; i++) {
                int v = i * 256 + tid;
                int r = v >> 4, c = v & 15;
                wh[r * 17 + c] = __ldg(bh + v);
                wl[r * 17 + c] = __ldg(bo + v);
            }
        }
        __syncthreads();

        // --- compute: 3 split terms x 8 k-steps, ldmatrix fragments ---
#pragma unroll
        for (int term = 0; term < 3; term++) {
            unsigned Abase = sb + ((term == 1) ? OFF_ALO : OFF_AHI) + aoff;
            unsigned Bbase = sb + ((term == 2) ? OFF_WLO : OFF_WHI) + boff;
#pragma unroll
            for (int k0 = 0; k0 < 8; k0++) {
                unsigned a[2][4], b[8][2];
                ldsm4(a[0][0], a[0][1], a[0][2], a[0][3], Abase + k0 * 32);
                ldsm4(a[1][0], a[1][1], a[1][2], a[1][3], Abase + 16 * 272 + k0 * 32);
#pragma unroll
                for (int p = 0; p < 4; p++)
                    ldsm4(b[2 * p][0], b[2 * p][1], b[2 * p + 1][0], b[2 * p + 1][1],
                          Bbase + p * 16 * 272 + k0 * 32);
#pragma unroll
                for (int mi = 0; mi < 2; mi++)
#pragma unroll
                    for (int ni = 0; ni < 8; ni++)
                        mma16816(acc[mi][ni], a[mi], b[ni]);
            }
        }
        __syncthreads();
    }

    // --- epilogue: acc -> SMEM fp32 tile, then one thread per row ---
    float* smC = (float*)smem;
    const int g = lane >> 2, t4 = lane & 3;
#pragma unroll
    for (int mi = 0; mi < 2; mi++)
#pragma unroll
        for (int ni = 0; ni < 8; ni++) {
            int row = m0 + mi * 16 + g;
            int col = n0 + ni * 8 + t4 * 2;
            smC[row * CSTRIDE + col]           = acc[mi][ni][0];
            smC[row * CSTRIDE + col + 1]       = acc[mi][ni][1];
            smC[(row + 8) * CSTRIDE + col]     = acc[mi][ni][2];
            smC[(row + 8) * CSTRIDE + col + 1] = acc[mi][ni][3];
        }
    __syncthreads();

    if (tid < 128) {
        int row = rowBase + tid;
        float d[128];
#pragma unroll
        for (int c = 0; c < 128; c += 4) {
            float4 v = *(const float4*)(smC + tid * CSTRIDE + c);
            float4 bb = __ldg((const float4*)(bl + c));
            d[c]     = v.x + bb.x;
            d[c + 1] = v.y + bb.y;
            d[c + 2] = v.z + bb.z;
            d[c + 3] = v.w + bb.w;
        }
        if (donorm) {
            float s = 0.f;
#pragma unroll
            for (int c = 0; c < 128; c++) s = fmaf(d[c], d[c], s);
            float inv = 1.0f / fmaxf(sqrtf(s), 1e-12f);
#pragma unroll
            for (int c = 0; c < 128; c++) d[c] *= inv;
        }
        if (row < NN) {
            float* op = out + (size_t)row * 128;
#pragma unroll
            for (int c = 0; c < 128; c += 4)
                *(float4*)(op + c) = make_float4(d[c], d[c + 1], d[c + 2], d[c + 3]);
        }
    }
}

// ---------------- global add pool (batch sorted -> binary search) --------------
__global__ void k_pool(const float* __restrict__ h, const int* __restrict__ batch) {
    int gi = blockIdx.x;
    int lo, hi;
    { int a = 0, b = NN; while (a < b) { int m = (a + b) >> 1; if (batch[m] < gi) a = m + 1; else b = m; } lo = a; }
    { int a = lo, b = NN; while (a < b) { int m = (a + b) >> 1; if (batch[m] < gi + 1) a = m + 1; else b = m; } hi = a; }
    int t = threadIdx.x;
    float s = 0.f;
    for (int n = lo; n < hi; n++) s += h[(size_t)n * 128 + t];
    g_pool[gi * 128 + t] = s;
}

// ---------------- MLP head ----------------
__global__ void k_mlp(const float* __restrict__ W0, const float* __restrict__ b0,
                      const float* __restrict__ W1, const float* __restrict__ b1,
                      const float* __restrict__ Wh, const float* __restrict__ bh,
                      float* __restrict__ out) {
    int gi = blockIdx.x, t = threadIdx.x;
    __shared__ float r0[128], r1[128];
    __shared__ float ws[4];
    r0[t] = g_pool[gi * 128 + t];
    __syncthreads();
    float s = b0[t];
#pragma unroll 8
    for (int k = 0; k < 128; k++) s = fmaf(r0[k], W0[k * 128 + t], s);
    r1[t] = fmaxf(s, 0.f);
    __syncthreads();
    float s2 = b1[t];
#pragma unroll 8
    for (int k = 0; k < 128; k++) s2 = fmaf(r1[k], W1[k * 128 + t], s2);
    float h = fmaxf(s2, 0.f);
    float p = h * Wh[t];
#pragma unroll
    for (int o = 16; o; o >>= 1) p += __shfl_xor_sync(0xffffffffu, p, o);
    if ((t & 31) == 0) ws[t >> 5] = p;
    __syncthreads();
    if (t == 0) out[gi] = ws[0] + ws[1] + ws[2] + ws[3] + bh[0];
}

// ---------------- orchestration ----------------
extern "C" void kernel_launch(void* const* d_in, const int* in_sizes, int n_in,
                              void* d_out, int out_size) {
    const float* x    = (const float*)d_in[0];
    const int*  eic   = (const int*)d_in[1];
    const int*  eid   = (const int*)d_in[2];
    const int*  eit   = (const int*)d_in[3];
    const int*  batch = (const int*)d_in[4];
    const float* cWl[5], *cbl[5], *cWr[5];
    for (int c = 0; c < 5; c++) {
        cWl[c] = (const float*)d_in[5 + 3 * c];
        cbl[c] = (const float*)d_in[6 + 3 * c];
        cWr[c] = (const float*)d_in[7 + 3 * c];
    }
    const float* l0W = (const float*)d_in[20];
    const float* l0b = (const float*)d_in[21];
    const float* l1W = (const float*)d_in[22];
    const float* l1b = (const float*)d_in[23];
    const float* hW  = (const float*)d_in[24];
    const float* hb  = (const float*)d_in[25];
    float* out = (float*)d_out;

    float *hA = nullptr, *hB = nullptr;
    cudaGetSymbolAddress((void**)&hA, g_hA);
    cudaGetSymbolAddress((void**)&hB, g_hB);

    cudaFuncSetAttribute(k_sage_mma, cudaFuncAttributeMaxDynamicSharedMemorySize, SM_TOTAL);

    // CSR build (3 edge lists)
    k_zero_deg<<<(3 * NN + 255) / 256, 256>>>();
    k_hist<<<(EE + 255) / 256, 256>>>(eic, eid, eit);
    k_scan<<<3, 1024>>>();
    k_fill3<<<(3 * EE + 255) / 256, 256>>>(eic, eid, eit);

    // weight blobs (bf16 hi/lo, transposed to [n][k]) - single launch
    WP wp;
    for (int c = 0; c < 5; c++) { wp.p[2 * c] = cWl[c]; wp.p[2 * c + 1] = cWr[c]; }
    k_wprep_all<<<640, 256>>>(wp);

    const int lst[7]  = {1, 0, 0, 2, 1, 0, 0};
    const int conv[7] = {0, 1, 1, 2, 3, 4, 4};
    const int nrm[7]  = {1, 1, 1, 0, 1, 1, 1};

    const float* hin = x;
    float* hout = hA;
    for (int L = 0; L < 7; L++) {
        k_sage_mma<<<(NN + 127) / 128, 256, SM_TOTAL>>>(hin, cbl[conv[L]], conv[L],
                                                        lst[L], hout, nrm[L]);
        hin = hout;
        hout = (hout == hA) ? hB : hA;
    }

    k_pool<<<NG, 128>>>(hin, batch);
    k_mlp<<<NG, 128>>>(l0W, l0b, l1W, l1b, hW, hb, out);
}

// round 9
// speedup vs baseline: 1.7202x; 1.7202x over previous
#include <cuda_runtime.h>
#include <cuda_bf16.h>

#define NN 50000
#define EE 600000
#define HH 128
#define NG 64

// ---------------- static scratch (allocation-free rule) ----------------
__device__ float g_agg[NN * HH];
__device__ float g_hA[NN * HH];
__device__ float g_hB[NN * HH];
__device__ int   g_deg[3][NN];
__device__ int   g_off[3][NN + 1];
__device__ int   g_cur[3][NN];
__device__ int   g_csr[3][EE];
__device__ float g_pool[NG * HH];
// bf16 weight images, transposed to [n][k] row-major, unpadded 32KB each:
// [conv][mat(Wl=0,Wr=1)][hi=0/lo=1]
__device__ __align__(16) __nv_bfloat16 g_wblob[5][2][2][HH * HH];

// ---------------- CSR build ----------------
__global__ void k_zero_deg() {
    int i = blockIdx.x * blockDim.x + threadIdx.x;
    if (i < 3 * NN) ((int*)g_deg)[i] = 0;
}
__global__ void k_hist(const int* __restrict__ e0, const int* __restrict__ e1,
                       const int* __restrict__ e2) {
    int i = blockIdx.x * blockDim.x + threadIdx.x;
    if (i >= EE) return;
    atomicAdd(&g_deg[0][e0[EE + i]], 1);
    atomicAdd(&g_deg[1][e1[EE + i]], 1);
    atomicAdd(&g_deg[2][e2[EE + i]], 1);
}
__global__ void k_scan() {
    int lst = blockIdx.x;
    __shared__ int wsum[32];
    __shared__ int carry;
    int t = threadIdx.x, wid = t >> 5, lane = t & 31;
    if (t == 0) carry = 0;
    __syncthreads();
    for (int base = 0; base < NN; base += 1024) {
        int i = base + t;
        int v = (i < NN) ? g_deg[lst][i] : 0;
        int x = v;
#pragma unroll
        for (int o = 1; o < 32; o <<= 1) {
            int y = __shfl_up_sync(0xffffffffu, x, o);
            if (lane >= o) x += y;
        }
        __syncthreads();
        if (lane == 31) wsum[wid] = x;
        __syncthreads();
        if (t < 32) {
            int xx = wsum[t];
#pragma unroll
            for (int o = 1; o < 32; o <<= 1) {
                int y = __shfl_up_sync(0xffffffffu, xx, o);
                if (t >= o) xx += y;
            }
            wsum[t] = xx;
        }
        __syncthreads();
        int wb = wid ? wsum[wid - 1] : 0;
        int excl = carry + wb + x - v;
        if (i < NN) { g_off[lst][i] = excl; g_cur[lst][i] = excl; }
        __syncthreads();
        if (t == 0) carry += wsum[31];
        __syncthreads();
    }
    if (t == 0) g_off[lst][NN] = carry;
}
// all 3 lists in one launch
__global__ void k_fill3(const int* __restrict__ e0, const int* __restrict__ e1,
                        const int* __restrict__ e2) {
    int i = blockIdx.x * blockDim.x + threadIdx.x;
    if (i < EE) {
        int d = e0[EE + i];
        g_csr[0][atomicAdd(&g_cur[0][d], 1)] = e0[i];
    } else if (i < 2 * EE) {
        int j = i - EE;
        int d = e1[EE + j];
        g_csr[1][atomicAdd(&g_cur[1][d], 1)] = e1[j];
    } else if (i < 3 * EE) {
        int j = i - 2 * EE;
        int d = e2[EE + j];
        g_csr[2][atomicAdd(&g_cur[2][d], 1)] = e2[j];
    }
}

// ---------------- mean aggregation: warp per node, high occupancy ----------------
__global__ void k_agg(const float* __restrict__ h, int lst) {
    int node = (blockIdx.x * blockDim.x + threadIdx.x) >> 5;
    if (node >= NN) return;
    int lane = threadIdx.x & 31;
    int s = g_off[lst][node], e = g_off[lst][node + 1];
    const int* csr = g_csr[lst];
    float4 acc = make_float4(0.f, 0.f, 0.f, 0.f);
    for (int i = s; i < e; i++) {
        int src = csr[i];
        float4 v = __ldg((const float4*)(h + (size_t)src * HH + lane * 4));
        acc.x += v.x; acc.y += v.y; acc.z += v.z; acc.w += v.w;
    }
    float inv = 1.0f / fmaxf((float)(e - s), 1.0f);
    acc.x *= inv; acc.y *= inv; acc.z *= inv; acc.w *= inv;
    *(float4*)(g_agg + (size_t)node * HH + lane * 4) = acc;
}

// ---------------- weight prep: all 10 matrices in one launch ----------------
struct WP { const float* p[10]; };
__global__ void k_wprep_all(WP wp) {
    int idx = blockIdx.x * blockDim.x + threadIdx.x;  // 0..163839
    int m = idx >> 14;            // 0..9 -> conv*2 + mat
    int r = idx & 16383;
    int n = r >> 7, k = r & 127;
    const float* W = wp.p[m];
    float v = W[k * 128 + n];
    __nv_bfloat16 hi = __float2bfloat16(v);
    __nv_bfloat16 lo = __float2bfloat16(v - __bfloat162float(hi));
    int c = m >> 1, mat = m & 1;
    g_wblob[c][mat][0][n * 128 + k] = hi;
    g_wblob[c][mat][1][n * 128 + k] = lo;
}

// ---------------- mma.sync bf16 SAGE GEMM (ldmatrix fragments) ----------------
// out[128 x 128] = agg@Wl + hin@Wr + bl (+ optional row L2 norm)
// 3-term bf16 split per phase: hi*hi + lo*hi + hi*lo, fp32 accum.
// SMEM: 4 bf16 tiles [128][128], row stride 272B -> LDS/LDSM conflict-free.
#define PADW 68
#define TILE_B (128 * PADW * 4)
#define OFF_AHI 0
#define OFF_ALO TILE_B
#define OFF_WHI (2 * TILE_B)
#define OFF_WLO (3 * TILE_B)
#define SM_TOTAL (4 * TILE_B)
#define CSTRIDE 132

__device__ __forceinline__ unsigned smem_u32(const void* p) {
    unsigned a;
    asm("{ .reg .u64 t; cvta.to.shared.u64 t, %1; cvt.u32.u64 %0, t; }" : "=r"(a) : "l"(p));
    return a;
}
__device__ __forceinline__ void mma16816(float* c, const unsigned* a, const unsigned* b) {
    asm volatile(
        "mma.sync.aligned.m16n8k16.row.col.f32.bf16.bf16.f32 "
        "{%0,%1,%2,%3}, {%4,%5,%6,%7}, {%8,%9}, {%0,%1,%2,%3};"
        : "+f"(c[0]), "+f"(c[1]), "+f"(c[2]), "+f"(c[3])
        : "r"(a[0]), "r"(a[1]), "r"(a[2]), "r"(a[3]), "r"(b[0]), "r"(b[1]));
}
__device__ __forceinline__ void ldsm4(unsigned& r0, unsigned& r1, unsigned& r2,
                                      unsigned& r3, unsigned addr) {
    asm volatile("ldmatrix.sync.aligned.m8n8.x4.shared.b16 {%0,%1,%2,%3}, [%4];"
                 : "=r"(r0), "=r"(r1), "=r"(r2), "=r"(r3) : "r"(addr));
}

__global__ __launch_bounds__(256, 1) void k_sage_mma(
    const float* __restrict__ hin, const float* __restrict__ bl,
    int conv, float* __restrict__ out, int donorm) {
    extern __shared__ char smem[];
    const unsigned sb = smem_u32(smem);
    const int tid = threadIdx.x;
    const int wid = tid >> 5, lane = tid & 31;
    const int m0 = (wid >> 1) * 32;       // warp m-origin
    const int n0 = (wid & 1) * 64;        // warp n-origin
    const int rowBase = blockIdx.x * 128;

    float acc[2][8][4];
#pragma unroll
    for (int mi = 0; mi < 2; mi++)
#pragma unroll
        for (int ni = 0; ni < 8; ni++)
#pragma unroll
            for (int r = 0; r < 4; r++) acc[mi][ni][r] = 0.f;

    // per-lane ldmatrix base offsets (bytes within a tile)
    const int i4 = lane >> 3, r8 = lane & 7;
    const unsigned aoff = (unsigned)(m0 + (i4 & 1) * 8 + r8) * 272 + (i4 >> 1) * 16;
    const unsigned boff = (unsigned)(n0 + (i4 >> 1) * 8 + r8) * 272 + (i4 & 1) * 16;

#pragma unroll 1
    for (int phase = 0; phase < 2; phase++) {
        const float* A = phase ? hin : g_agg;
        // --- A tile: fp32 load -> bf16 hi/lo split into padded SMEM ---
#pragma unroll 4
        for (int i = 0; i < 16; i++) {
            int v = i * 256 + tid;        // 4096 float4 per 128x128 tile
            int r = v >> 5, c4 = v & 31;
            int grow = rowBase + r;
            float4 f = make_float4(0.f, 0.f, 0.f, 0.f);
            if (grow < NN) f = __ldg((const float4*)(A + (size_t)grow * HH + c4 * 4));
            __nv_bfloat162 h0, h1, l0, l1;
            h0.x = __float2bfloat16(f.x); h0.y = __float2bfloat16(f.y);
            h1.x = __float2bfloat16(f.z); h1.y = __float2bfloat16(f.w);
            l0.x = __float2bfloat16(f.x - __bfloat162float(h0.x));
            l0.y = __float2bfloat16(f.y - __bfloat162float(h0.y));
            l1.x = __float2bfloat16(f.z - __bfloat162float(h1.x));
            l1.y = __float2bfloat16(f.w - __bfloat162float(h1.y));
            unsigned so = (unsigned)r * 272 + c4 * 8;
            *(__nv_bfloat162*)(smem + OFF_AHI + so)     = h0;
            *(__nv_bfloat162*)(smem + OFF_AHI + so + 4) = h1;
            *(__nv_bfloat162*)(smem + OFF_ALO + so)     = l0;
            *(__nv_bfloat162*)(smem + OFF_ALO + so + 4) = l1;
        }
        // --- W tiles: copy hi/lo blobs into padded SMEM ---
        {
            const uint4* bh = (const uint4*)g_wblob[conv][phase][0];
            const uint4* bo = (const uint4*)g_wblob[conv][phase][1];
            uint4* wh = (uint4*)(smem + OFF_WHI);
            uint4* wl = (uint4*)(smem + OFF_WLO);
#pragma unroll 4
            for (int i = 0; i < 8; i++) {
                int v = i * 256 + tid;
                int r = v >> 4, c = v & 15;
                wh[r * 17 + c] = __ldg(bh + v);
                wl[r * 17 + c] = __ldg(bo + v);
            }
        }
        __syncthreads();

        // --- compute: 3 split terms x 8 k-steps, ldmatrix fragments ---
#pragma unroll
        for (int term = 0; term < 3; term++) {
            unsigned Abase = sb + ((term == 1) ? OFF_ALO : OFF_AHI) + aoff;
            unsigned Bbase = sb + ((term == 2) ? OFF_WLO : OFF_WHI) + boff;
#pragma unroll
            for (int k0 = 0; k0 < 8; k0++) {
                unsigned a[2][4], b[8][2];
                ldsm4(a[0][0], a[0][1], a[0][2], a[0][3], Abase + k0 * 32);
                ldsm4(a[1][0], a[1][1], a[1][2], a[1][3], Abase + 16 * 272 + k0 * 32);
#pragma unroll
                for (int p = 0; p < 4; p++)
                    ldsm4(b[2 * p][0], b[2 * p][1], b[2 * p + 1][0], b[2 * p + 1][1],
                          Bbase + p * 16 * 272 + k0 * 32);
#pragma unroll
                for (int mi = 0; mi < 2; mi++)
#pragma unroll
                    for (int ni = 0; ni < 8; ni++)
                        mma16816(acc[mi][ni], a[mi], b[ni]);
            }
        }
        __syncthreads();
    }

    // --- epilogue: acc -> SMEM fp32 tile, then one thread per row ---
    float* smC = (float*)smem;
    const int g = lane >> 2, t4 = lane & 3;
#pragma unroll
    for (int mi = 0; mi < 2; mi++)
#pragma unroll
        for (int ni = 0; ni < 8; ni++) {
            int row = m0 + mi * 16 + g;
            int col = n0 + ni * 8 + t4 * 2;
            smC[row * CSTRIDE + col]           = acc[mi][ni][0];
            smC[row * CSTRIDE + col + 1]       = acc[mi][ni][1];
            smC[(row + 8) * CSTRIDE + col]     = acc[mi][ni][2];
            smC[(row + 8) * CSTRIDE + col + 1] = acc[mi][ni][3];
        }
    __syncthreads();

    if (tid < 128) {
        int row = rowBase + tid;
        float d[128];
#pragma unroll
        for (int c = 0; c < 128; c += 4) {
            float4 v = *(const float4*)(smC + tid * CSTRIDE + c);
            float4 bb = __ldg((const float4*)(bl + c));
            d[c]     = v.x + bb.x;
            d[c + 1] = v.y + bb.y;
            d[c + 2] = v.z + bb.z;
            d[c + 3] = v.w + bb.w;
        }
        if (donorm) {
            float s = 0.f;
#pragma unroll
            for (int c = 0; c < 128; c++) s = fmaf(d[c], d[c], s);
            float inv = 1.0f / fmaxf(sqrtf(s), 1e-12f);
#pragma unroll
            for (int c = 0; c < 128; c++) d[c] *= inv;
        }
        if (row < NN) {
            float* op = out + (size_t)row * 128;
#pragma unroll
            for (int c = 0; c < 128; c += 4)
                *(float4*)(op + c) = make_float4(d[c], d[c + 1], d[c + 2], d[c + 3]);
        }
    }
}

// ---------------- global add pool (batch sorted -> binary search) --------------
__global__ void k_pool(const float* __restrict__ h, const int* __restrict__ batch) {
    int gi = blockIdx.x;
    int lo, hi;
    { int a = 0, b = NN; while (a < b) { int m = (a + b) >> 1; if (batch[m] < gi) a = m + 1; else b = m; } lo = a; }
    { int a = lo, b = NN; while (a < b) { int m = (a + b) >> 1; if (batch[m] < gi + 1) a = m + 1; else b = m; } hi = a; }
    int t = threadIdx.x;
    float s = 0.f;
    for (int n = lo; n < hi; n++) s += h[(size_t)n * 128 + t];
    g_pool[gi * 128 + t] = s;
}

// ---------------- MLP head ----------------
__global__ void k_mlp(const float* __restrict__ W0, const float* __restrict__ b0,
                      const float* __restrict__ W1, const float* __restrict__ b1,
                      const float* __restrict__ Wh, const float* __restrict__ bh,
                      float* __restrict__ out) {
    int gi = blockIdx.x, t = threadIdx.x;
    __shared__ float r0[128], r1[128];
    __shared__ float ws[4];
    r0[t] = g_pool[gi * 128 + t];
    __syncthreads();
    float s = b0[t];
#pragma unroll 8
    for (int k = 0; k < 128; k++) s = fmaf(r0[k], W0[k * 128 + t], s);
    r1[t] = fmaxf(s, 0.f);
    __syncthreads();
    float s2 = b1[t];
#pragma unroll 8
    for (int k = 0; k < 128; k++) s2 = fmaf(r1[k], W1[k * 128 + t], s2);
    float h = fmaxf(s2, 0.f);
    float p = h * Wh[t];
#pragma unroll
    for (int o = 16; o; o >>= 1) p += __shfl_xor_sync(0xffffffffu, p, o);
    if ((t & 31) == 0) ws[t >> 5] = p;
    __syncthreads();
    if (t == 0) out[gi] = ws[0] + ws[1] + ws[2] + ws[3] + bh[0];
}

// ---------------- orchestration ----------------
extern "C" void kernel_launch(void* const* d_in, const int* in_sizes, int n_in,
                              void* d_out, int out_size) {
    const float* x    = (const float*)d_in[0];
    const int*  eic   = (const int*)d_in[1];
    const int*  eid   = (const int*)d_in[2];
    const int*  eit   = (const int*)d_in[3];
    const int*  batch = (const int*)d_in[4];
    const float* cWl[5], *cbl[5], *cWr[5];
    for (int c = 0; c < 5; c++) {
        cWl[c] = (const float*)d_in[5 + 3 * c];
        cbl[c] = (const float*)d_in[6 + 3 * c];
        cWr[c] = (const float*)d_in[7 + 3 * c];
    }
    const float* l0W = (const float*)d_in[20];
    const float* l0b = (const float*)d_in[21];
    const float* l1W = (const float*)d_in[22];
    const float* l1b = (const float*)d_in[23];
    const float* hW  = (const float*)d_in[24];
    const float* hb  = (const float*)d_in[25];
    float* out = (float*)d_out;

    float *hA = nullptr, *hB = nullptr;
    cudaGetSymbolAddress((void**)&hA, g_hA);
    cudaGetSymbolAddress((void**)&hB, g_hB);

    cudaFuncSetAttribute(k_sage_mma, cudaFuncAttributeMaxDynamicSharedMemorySize, SM_TOTAL);

    // CSR build (3 edge lists)
    k_zero_deg<<<(3 * NN + 255) / 256, 256>>>();
    k_hist<<<(EE + 255) / 256, 256>>>(eic, eid, eit);
    k_scan<<<3, 1024>>>();
    k_fill3<<<(3 * EE + 255) / 256, 256>>>(eic, eid, eit);

    // weight blobs (bf16 hi/lo, transposed to [n][k]) - single launch
    WP wp;
    for (int c = 0; c < 5; c++) { wp.p[2 * c] = cWl[c]; wp.p[2 * c + 1] = cWr[c]; }
    k_wprep_all<<<640, 256>>>(wp);

    const int lst[7]  = {1, 0, 0, 2, 1, 0, 0};
    const int conv[7] = {0, 1, 1, 2, 3, 4, 4};
    const int nrm[7]  = {1, 1, 1, 0, 1, 1, 1};

    const float* hin = x;
    float* hout = hA;
    for (int L = 0; L < 7; L++) {
        k_agg<<<(NN * 32 + 255) / 256, 256>>>(hin, lst[L]);
        k_sage_mma<<<(NN + 127) / 128, 256, SM_TOTAL>>>(hin, cbl[conv[L]], conv[L],
                                                        hout, nrm[L]);
        hin = hout;
        hout = (hout == hA) ? hB : hA;
    }

    k_pool<<<NG, 128>>>(hin, batch);
    k_mlp<<<NG, 128>>>(l0W, l0b, l1W, l1b, hW, hb, out);
}